// round 2
// baseline (speedup 1.0000x reference)
#include <cuda_runtime.h>
#include <math.h>

// ---------------- problem constants ----------------
#define BB    16
#define NN    1024
#define DD    64
#define EPSF  0.1f
#define MAXIT 100
#define THRF  0.1f
#define GRD   128     // persistent grid (<= 148 SMs, full residency guaranteed)
#define TPB   512

// ---------------- device scratch (no allocs allowed) ----------------
__device__ float g_xs[BB * NN * DD];            // softmaxed x   (4 MB)
__device__ float g_ys[BB * NN * DD];            // softmaxed y   (4 MB)
__device__ float g_x2[BB * NN];
__device__ float g_y2[BB * NN];
__device__ float g_C[(size_t)BB * NN * NN];     // cost matrix   (64 MB)
__device__ float g_K[(size_t)BB * NN * NN];     // exp(-C/eps)   (64 MB, L2-resident)
__device__ float g_u[BB * NN];
__device__ float g_v[BB * NN];
__device__ float g_a[BB * NN];                  // exp(u/eps)
__device__ float g_bv[BB * NN];                 // exp(v/eps)
__device__ float g_errPart[GRD];
__device__ double g_cost;
__device__ unsigned g_bar;

// ---------------- init (must run every replay: graph replays reuse globals) ----
__global__ void init_kernel() {
    int t = blockIdx.x * blockDim.x + threadIdx.x;
    int stride = gridDim.x * blockDim.x;
    for (int i = t; i < BB * NN; i += stride) {
        g_u[i] = 0.0f;
        g_v[i] = 0.0f;
        g_a[i] = 1.0f;
        g_bv[i] = 1.0f;
    }
    if (t == 0) {
        g_cost = 0.0;
        g_bar = 0u;
    }
}

// ---------------- softmax of x and y (one warp per row of 64) ----------------
__global__ void softmax_kernel(const float* __restrict__ x,
                               const float* __restrict__ y) {
    int w = (blockIdx.x * blockDim.x + threadIdx.x) >> 5;   // global warp id
    int lane = threadIdx.x & 31;
    const float* src;
    float* dst;
    float* nrm;
    int row;
    if (w < BB * NN) { row = w;            src = x; dst = g_xs; nrm = g_x2; }
    else             { row = w - BB * NN;  src = y; dst = g_ys; nrm = g_y2; }

    const float2* r = (const float2*)(src + (size_t)row * DD);
    float2 v = r[lane];
    float m = fmaxf(v.x, v.y);
    #pragma unroll
    for (int o = 16; o; o >>= 1) m = fmaxf(m, __shfl_xor_sync(0xffffffffu, m, o));
    float e0 = expf(v.x - m), e1 = expf(v.y - m);
    float s = e0 + e1;
    #pragma unroll
    for (int o = 16; o; o >>= 1) s += __shfl_xor_sync(0xffffffffu, s, o);
    float inv = 1.0f / s;
    float p0 = e0 * inv, p1 = e1 * inv;
    ((float2*)(dst + (size_t)row * DD))[lane] = make_float2(p0, p1);
    float q = p0 * p0 + p1 * p1;
    #pragma unroll
    for (int o = 16; o; o >>= 1) q += __shfl_xor_sync(0xffffffffu, q, o);
    if (lane == 0) nrm[row] = q;
}

// ---------------- C = x2 + y2 - 2*X@Y^T ; K = exp(-C/eps) -----------------
// 128x128 tile per block, 256 threads, 8x8 micro-tile, k split into 2 stages.
__global__ void __launch_bounds__(256) gemm_kernel() {
    __shared__ float Xs[32][132];   // [k][i], padded: rows 16B aligned, few conflicts
    __shared__ float Ys[32][132];   // [k][j]
    const int b  = blockIdx.z;
    const int i0 = blockIdx.y * 128;
    const int j0 = blockIdx.x * 128;
    const int t  = threadIdx.x;
    const int tx = t & 15;          // j direction
    const int ty = t >> 4;          // i direction
    const float* __restrict__ Xb = g_xs + ((size_t)b * NN + i0) * DD;
    const float* __restrict__ Yb = g_ys + ((size_t)b * NN + j0) * DD;

    float acc[8][8];
    #pragma unroll
    for (int r = 0; r < 8; r++)
        #pragma unroll
        for (int c = 0; c < 8; c++) acc[r][c] = 0.0f;

    for (int k0 = 0; k0 < DD; k0 += 32) {
        __syncthreads();
        #pragma unroll
        for (int c = 0; c < 16; c++) {
            int flat = c * 256 + t;
            int i = flat >> 5, k = flat & 31;       // warp reads 32 contiguous k
            Xs[k][i] = Xb[i * DD + k0 + k];
            Ys[k][i] = Yb[i * DD + k0 + k];
        }
        __syncthreads();
        #pragma unroll
        for (int k = 0; k < 32; k++) {
            const float4* xr = (const float4*)(&Xs[k][0]);
            const float4* yr = (const float4*)(&Ys[k][0]);
            float4 a0 = xr[ty * 2 + 0], a1 = xr[ty * 2 + 1];
            float4 b0 = yr[tx * 2 + 0], b1 = yr[tx * 2 + 1];
            float av[8] = {a0.x, a0.y, a0.z, a0.w, a1.x, a1.y, a1.z, a1.w};
            float bw[8] = {b0.x, b0.y, b0.z, b0.w, b1.x, b1.y, b1.z, b1.w};
            #pragma unroll
            for (int r = 0; r < 8; r++)
                #pragma unroll
                for (int c = 0; c < 8; c++)
                    acc[r][c] = fmaf(av[r], bw[c], acc[r][c]);
        }
    }

    #pragma unroll
    for (int r = 0; r < 8; r++) {
        int gi = i0 + ty * 8 + r;
        float x2i = g_x2[b * NN + gi];
        size_t base = ((size_t)b * NN + gi) * NN + j0 + tx * 8;
        #pragma unroll
        for (int c = 0; c < 8; c++) {
            float cij = x2i + g_y2[b * NN + j0 + tx * 8 + c] - 2.0f * acc[r][c];
            g_C[base + c] = cij;
            g_K[base + c] = __expf(-10.0f * cij);   // exp(-C/eps), eps=0.1
        }
    }
}

// ---------------- software grid barrier (all GRD blocks resident) ------------
__device__ __forceinline__ void grid_barrier(unsigned& target) {
    target += GRD;
    __syncthreads();
    if (threadIdx.x == 0) {
        __threadfence();
        atomicAdd(&g_bar, 1u);
        volatile unsigned* p = &g_bar;
        while (*p < target) { __nanosleep(64); }
        __threadfence();
    }
    __syncthreads();
}

// ---------------- persistent Sinkhorn loop + final cost ----------------------
__global__ void __launch_bounds__(TPB) sinkhorn_kernel(float* __restrict__ out) {
    __shared__ float shA[NN];       // bvec (phase A) / avec (phase B)
    __shared__ float shP[NN];       // column partials: [16 warps][64 cols]
    __shared__ float shRed[16];
    __shared__ float shErr;
    const int tid  = threadIdx.x;
    const int w    = tid >> 5;
    const int lane = tid & 31;
    const int bid  = blockIdx.x;
    unsigned target = 0;
    const float log_mu  = logf(1.0f / NN + 1e-8f);
    const float inv_eps = 1.0f / EPSF;
    bool stop = false;

    for (int it = 0; it < MAXIT && !stop; ++it) {
        // ===== phase A: row pass, u update =====
        // block owns 128 consecutive rows -> single batch; cache its bvec
        const int rowBatch = bid >> 3;
        {
            const float* __restrict__ bv = g_bv + rowBatch * NN;
            for (int i = tid; i < NN; i += TPB) shA[i] = bv[i];
        }
        __syncthreads();
        float errAcc = 0.0f;
        const int rowBase = bid * 128 + w * 8;   // one warp -> 8 rows
        #pragma unroll 1
        for (int r = 0; r < 8; r++) {
            const int row = rowBase + r;
            const float4* __restrict__ Kr  = (const float4*)(g_K + (size_t)row * NN);
            const float4* __restrict__ bv4 = (const float4*)shA;
            float s0 = 0.f, s1 = 0.f, s2 = 0.f, s3 = 0.f;
            #pragma unroll
            for (int k = 0; k < 8; k++) {
                float4 kv = Kr[lane + 32 * k];
                float4 b4 = bv4[lane + 32 * k];
                s0 = fmaf(kv.x, b4.x, s0);
                s1 = fmaf(kv.y, b4.y, s1);
                s2 = fmaf(kv.z, b4.z, s2);
                s3 = fmaf(kv.w, b4.w, s3);
            }
            float s = (s0 + s1) + (s2 + s3);
            #pragma unroll
            for (int o = 16; o; o >>= 1) s += __shfl_xor_sync(0xffffffffu, s, o);
            if (lane == 0) {
                float uo  = g_u[row];
                float ao  = __expf(uo * inv_eps);
                float lse = logf(fmaf(ao, s, 1e-6f));  // log(sum exp(M) + 1e-6)
                float un  = EPSF * (log_mu - lse) + uo;
                g_u[row] = un;
                g_a[row] = __expf(un * inv_eps);
                errAcc += fabsf(un - uo);
            }
        }
        if (lane == 0) shRed[w] = errAcc;
        __syncthreads();
        if (tid == 0) {
            float e = 0.f;
            #pragma unroll
            for (int i = 0; i < 16; i++) e += shRed[i];
            g_errPart[bid] = e;                      // deterministic, no atomics
        }
        grid_barrier(target);

        // ===== phase B: column pass, v update (2 tiles of 64 cols per block) =====
        for (int sidx = 0; sidx < 2; sidx++) {
            const int tile = bid + sidx * GRD;        // 0..255
            const int tb   = tile >> 4;               // batch
            const int j0   = (tile & 15) * 64;
            __syncthreads();
            {
                const float* __restrict__ av = g_a + tb * NN;
                for (int i = tid; i < NN; i += TPB) shA[i] = av[i];
            }
            __syncthreads();
            const float2* __restrict__ K2 =
                (const float2*)(g_K + (size_t)tb * NN * NN);
            float ax = 0.f, ay = 0.f;
            const int ib = w * 64;                    // warp covers 64 rows
            #pragma unroll 4
            for (int ii = 0; ii < 64; ii++) {
                int i = ib + ii;
                float2 kv = K2[(size_t)i * (NN / 2) + (j0 >> 1) + lane];
                float ai = shA[i];
                ax = fmaf(kv.x, ai, ax);
                ay = fmaf(kv.y, ai, ay);
            }
            shP[w * 64 + 2 * lane]     = ax;
            shP[w * 64 + 2 * lane + 1] = ay;
            __syncthreads();
            if (tid < 64) {
                float tj = 0.f;
                #pragma unroll
                for (int ww = 0; ww < 16; ww++) tj += shP[ww * 64 + tid];
                int j = tb * NN + j0 + tid;
                float vo  = g_v[j];
                float bo  = __expf(vo * inv_eps);
                float lse = logf(fmaf(bo, tj, 1e-6f));
                float vn  = EPSF * (log_mu - lse) + vo;
                g_v[j]  = vn;
                g_bv[j] = __expf(vn * inv_eps);
            }
        }

        // ===== stop check (identical fixed-order reduction in every block) =====
        __syncthreads();
        float ev = (tid < GRD) ? g_errPart[tid] : 0.0f;
        #pragma unroll
        for (int o = 16; o; o >>= 1) ev += __shfl_xor_sync(0xffffffffu, ev, o);
        if (lane == 0) shRed[w] = ev;
        __syncthreads();
        if (tid == 0) shErr = shRed[0] + shRed[1] + shRed[2] + shRed[3];
        __syncthreads();
        stop = (shErr * (1.0f / BB) < THRF);          // err < THRESH -> stop
        grid_barrier(target);
    }

    // ===== final: cost = mean_b sum_ij exp((u+v-C)/eps) * C =====
    {
        float acc = 0.0f;
        const float4* __restrict__ C4 = (const float4*)g_C;
        const int total4 = BB * NN * NN / 4;
        for (int idx = bid * TPB + tid; idx < total4; idx += GRD * TPB) {
            int row = idx >> 8;                       // b*N + i
            int j4  = idx & 255;
            int bb  = row >> 10;
            float u = g_u[row];
            float4 c  = C4[idx];
            float4 vv = ((const float4*)(g_v + bb * NN))[j4];
            acc += __expf((u + vv.x - c.x) * inv_eps) * c.x;
            acc += __expf((u + vv.y - c.y) * inv_eps) * c.y;
            acc += __expf((u + vv.z - c.z) * inv_eps) * c.z;
            acc += __expf((u + vv.w - c.w) * inv_eps) * c.w;
        }
        #pragma unroll
        for (int o = 16; o; o >>= 1) acc += __shfl_xor_sync(0xffffffffu, acc, o);
        if (lane == 0) shRed[w] = acc;
        __syncthreads();
        if (tid == 0) {
            float e = 0.f;
            #pragma unroll
            for (int i = 0; i < 16; i++) e += shRed[i];
            atomicAdd(&g_cost, (double)e);
        }
        grid_barrier(target);
        if (bid == 0 && tid == 0) out[0] = (float)(g_cost * (1.0 / BB));
    }
}

// ---------------- launch ----------------
extern "C" void kernel_launch(void* const* d_in, const int* in_sizes, int n_in,
                              void* d_out, int out_size) {
    const float* x = (const float*)d_in[0];
    const float* y = (const float*)d_in[1];
    float* out = (float*)d_out;

    init_kernel<<<64, 256>>>();
    softmax_kernel<<<(2 * BB * NN) / 8, 256>>>(x, y);     // 1 warp / row
    gemm_kernel<<<dim3(8, 8, BB), 256>>>();
    sinkhorn_kernel<<<GRD, TPB>>>(out);
}

// round 3
// speedup vs baseline: 2.2363x; 2.2363x over previous
#include <cuda_runtime.h>
#include <cuda_fp16.h>
#include <math.h>

// ---------------- problem constants ----------------
#define BB    16
#define NN    1024
#define DD    64
#define EPSF  0.1f
#define MAXIT 100
#define THRF  0.1f
#define GRD   128
#define TPB   512

// ---------------- packed f32x2 helpers ----------------
typedef unsigned long long ull;
__device__ __forceinline__ ull pk2(float lo, float hi) {
    ull r; asm("mov.b64 %0, {%1, %2};" : "=l"(r) : "f"(lo), "f"(hi)); return r;
}
__device__ __forceinline__ void up2(ull v, float& lo, float& hi) {
    asm("mov.b64 {%0, %1}, %2;" : "=f"(lo), "=f"(hi) : "l"(v));
}
#define FMA2(d, a, b) asm("fma.rn.f32x2 %0, %1, %2, %0;" : "+l"(d) : "l"(a), "l"(b))

// ---------------- device scratch ----------------
__device__ float g_xs[BB * NN * DD];
__device__ float g_ys[BB * NN * DD];
__device__ float g_x2[BB * NN];
__device__ float g_y2[BB * NN];
__device__ float g_C[(size_t)BB * NN * NN];                 // 64 MB fp32
__device__ __align__(16) __half g_Kh[(size_t)BB * NN * NN]; // 32 MB fp16
__device__ float g_u[BB * NN];
__device__ float g_v[BB * NN];
__device__ float g_bv[BB * NN];                             // exp(v/eps)
__device__ float g_colPart[GRD * NN];                       // per-block col partials
__device__ float g_errPart[GRD];
__device__ double g_cost;
__device__ unsigned g_bar;

// ---------------- init ----------------
__global__ void init_kernel() {
    int t = blockIdx.x * blockDim.x + threadIdx.x;
    int stride = gridDim.x * blockDim.x;
    for (int i = t; i < BB * NN; i += stride) {
        g_u[i] = 0.0f; g_v[i] = 0.0f; g_bv[i] = 1.0f;
    }
    if (t == 0) { g_cost = 0.0; g_bar = 0u; }
}

// ---------------- softmax (1 warp per 64-elem row) ----------------
__global__ void softmax_kernel(const float* __restrict__ x,
                               const float* __restrict__ y) {
    int w = (blockIdx.x * blockDim.x + threadIdx.x) >> 5;
    int lane = threadIdx.x & 31;
    const float* src; float* dst; float* nrm; int row;
    if (w < BB * NN) { row = w;           src = x; dst = g_xs; nrm = g_x2; }
    else             { row = w - BB * NN; src = y; dst = g_ys; nrm = g_y2; }

    const float2* r = (const float2*)(src + (size_t)row * DD);
    float2 v = r[lane];
    float m = fmaxf(v.x, v.y);
    #pragma unroll
    for (int o = 16; o; o >>= 1) m = fmaxf(m, __shfl_xor_sync(0xffffffffu, m, o));
    float e0 = expf(v.x - m), e1 = expf(v.y - m);
    float s = e0 + e1;
    #pragma unroll
    for (int o = 16; o; o >>= 1) s += __shfl_xor_sync(0xffffffffu, s, o);
    float inv = 1.0f / s;
    float p0 = e0 * inv, p1 = e1 * inv;
    ((float2*)(dst + (size_t)row * DD))[lane] = make_float2(p0, p1);
    float q = p0 * p0 + p1 * p1;
    #pragma unroll
    for (int o = 16; o; o >>= 1) q += __shfl_xor_sync(0xffffffffu, q, o);
    if (lane == 0) nrm[row] = q;
}

// ---------------- GEMM: C = x2+y2-2XY^T, K = exp(-C/eps) (FFMA2 inner) ------
__global__ void __launch_bounds__(256) gemm_kernel() {
    __shared__ float Xs[32][132];
    __shared__ float Ys[32][132];
    const int b  = blockIdx.z;
    const int i0 = blockIdx.y * 128;
    const int j0 = blockIdx.x * 128;
    const int t  = threadIdx.x;
    const int tx = t & 15;
    const int ty = t >> 4;
    const float* __restrict__ Xb = g_xs + ((size_t)b * NN + i0) * DD;
    const float* __restrict__ Yb = g_ys + ((size_t)b * NN + j0) * DD;

    ull acc[8][4];
    #pragma unroll
    for (int r = 0; r < 8; r++)
        #pragma unroll
        for (int c = 0; c < 4; c++) acc[r][c] = 0ULL;   // bit pattern of (0,0)

    for (int k0 = 0; k0 < DD; k0 += 32) {
        __syncthreads();
        #pragma unroll
        for (int c = 0; c < 16; c++) {
            int flat = c * 256 + t;
            int i = flat >> 5, k = flat & 31;
            Xs[k][i] = Xb[i * DD + k0 + k];
            Ys[k][i] = Yb[i * DD + k0 + k];
        }
        __syncthreads();
        #pragma unroll
        for (int k = 0; k < 32; k++) {
            const float4* xr = (const float4*)(&Xs[k][0]);
            const ulonglong2* yr = (const ulonglong2*)(&Ys[k][0]);
            float4 a0 = xr[ty * 2 + 0], a1 = xr[ty * 2 + 1];
            ulonglong2 q0 = yr[tx * 2 + 0], q1 = yr[tx * 2 + 1];
            ull bw[4] = {q0.x, q0.y, q1.x, q1.y};
            float av[8] = {a0.x, a0.y, a0.z, a0.w, a1.x, a1.y, a1.z, a1.w};
            #pragma unroll
            for (int r = 0; r < 8; r++) {
                ull ap = pk2(av[r], av[r]);
                #pragma unroll
                for (int c = 0; c < 4; c++) FMA2(acc[r][c], ap, bw[c]);
            }
        }
    }

    float y2v[8];
    #pragma unroll
    for (int c = 0; c < 8; c++) y2v[c] = g_y2[b * NN + j0 + tx * 8 + c];

    #pragma unroll
    for (int r = 0; r < 8; r++) {
        int gi = i0 + ty * 8 + r;
        float x2i = g_x2[b * NN + gi];
        size_t base = ((size_t)b * NN + gi) * NN + j0 + tx * 8;
        float cv[8];
        #pragma unroll
        for (int cc = 0; cc < 4; cc++) {
            float lo, hi; up2(acc[r][cc], lo, hi);
            cv[2 * cc]     = x2i + y2v[2 * cc]     - 2.0f * lo;
            cv[2 * cc + 1] = x2i + y2v[2 * cc + 1] - 2.0f * hi;
        }
        *(float4*)(g_C + base)     = make_float4(cv[0], cv[1], cv[2], cv[3]);
        *(float4*)(g_C + base + 4) = make_float4(cv[4], cv[5], cv[6], cv[7]);
        union { __half2 h[4]; uint4 u; } kk;
        #pragma unroll
        for (int cc = 0; cc < 4; cc++)
            kk.h[cc] = __floats2half2_rn(__expf(-10.0f * cv[2 * cc]),
                                         __expf(-10.0f * cv[2 * cc + 1]));
        *(uint4*)(g_Kh + base) = kk.u;
    }
}

// ---------------- software grid barrier ----------------
__device__ __forceinline__ void grid_barrier(unsigned& target) {
    target += GRD;
    __syncthreads();
    if (threadIdx.x == 0) {
        __threadfence();
        atomicAdd(&g_bar, 1u);
        volatile unsigned* p = &g_bar;
        while (*p < target) { __nanosleep(32); }
        __threadfence();
    }
    __syncthreads();
}

// ---------------- fused persistent Sinkhorn + final cost ---------------------
// dynamic smem: shB[1024] | shCol[16*1026] | shRed[32]
#define COLSTRIDE 1026
#define SH_FLOATS (1024 + 16 * COLSTRIDE + 32)

__global__ void __launch_bounds__(TPB) sinkhorn_kernel(float* __restrict__ out) {
    extern __shared__ float sh[];
    float* shB   = sh;
    float* shCol = sh + 1024;
    float* shRed = shCol + 16 * COLSTRIDE;

    const int tid  = threadIdx.x;
    const int w    = tid >> 5;
    const int lane = tid & 31;
    const int bid  = blockIdx.x;
    unsigned target = 0;
    const float log_mu  = logf(1.0f / NN + 1e-8f);
    const float inv_eps = 1.0f / EPSF;
    bool stop = false;

    for (int it = 0; it < MAXIT && !stop; ++it) {
        // ===== fused sweep: u update + column partials in one K pass =====
        const int rowBatch = bid >> 3;
        {
            const float* __restrict__ bv = g_bv + rowBatch * NN;
            for (int i = tid; i < NN; i += TPB) shB[i] = bv[i];
        }
        __syncthreads();

        ull colAcc[16];
        #pragma unroll
        for (int q = 0; q < 16; q++) colAcc[q] = 0ULL;
        float errAcc = 0.0f;
        const int rowBase = bid * 128 + w * 8;

        #pragma unroll 1
        for (int r = 0; r < 8; r++) {
            const int row = rowBase + r;
            const uint4* __restrict__ Kr = (const uint4*)(g_Kh + (size_t)row * NN);
            ull kf[16];
            ull s2 = 0ULL;
            #pragma unroll
            for (int tt = 0; tt < 4; tt++) {
                uint4 q4 = Kr[lane + 32 * tt];
                const __half2* hp = (const __half2*)&q4;
                const ull* bp = (const ull*)(shB + ((lane + 32 * tt) << 3));
                #pragma unroll
                for (int e = 0; e < 4; e++) {
                    float2 f = __half22float2(hp[e]);
                    kf[tt * 4 + e] = pk2(f.x, f.y);
                    FMA2(s2, kf[tt * 4 + e], bp[e]);
                }
            }
            float sx, sy; up2(s2, sx, sy);
            float s = sx + sy;
            #pragma unroll
            for (int o = 16; o; o >>= 1) s += __shfl_xor_sync(0xffffffffu, s, o);

            float uo  = g_u[row];
            float ao  = __expf(uo * inv_eps);
            float lse = __logf(fmaf(ao, s, 1e-6f));
            float un  = EPSF * (log_mu - lse) + uo;
            float an  = __expf(un * inv_eps);
            if (lane == 0) { g_u[row] = un; errAcc += fabsf(un - uo); }
            ull ap = pk2(an, an);
            #pragma unroll
            for (int q = 0; q < 16; q++) FMA2(colAcc[q], ap, kf[q]);
        }

        // stash warp column partials + err
        if (lane == 0) shRed[w] = errAcc;
        {
            float* dst = shCol + w * COLSTRIDE;
            #pragma unroll
            for (int tt = 0; tt < 4; tt++) {
                int jb = (lane + 32 * tt) << 3;
                #pragma unroll
                for (int e = 0; e < 4; e++) {
                    float lo, hi; up2(colAcc[tt * 4 + e], lo, hi);
                    *(float2*)(dst + jb + 2 * e) = make_float2(lo, hi);
                }
            }
        }
        __syncthreads();

        // block-level column reduce over 16 warps -> global partials
        #pragma unroll
        for (int half = 0; half < 2; half++) {
            int j = tid + half * TPB;
            float sum = 0.0f;
            #pragma unroll
            for (int ww = 0; ww < 16; ww++) sum += shCol[ww * COLSTRIDE + j];
            g_colPart[bid * NN + j] = sum;
        }
        if (tid == 0) {
            float e = 0.f;
            #pragma unroll
            for (int i = 0; i < 16; i++) e += shRed[i];
            g_errPart[bid] = e;
        }
        grid_barrier(target);

        // ===== finalize v: sum 8 block-partials per (batch, col) =====
        if (tid < 128) {
            int g  = bid * 128 + tid;
            int tb = g >> 10;
            int j  = g & 1023;
            const float* cp = g_colPart + (size_t)(tb * 8) * NN + j;
            float s0 = cp[0 * NN] + cp[1 * NN];
            float s1 = cp[2 * NN] + cp[3 * NN];
            float s2 = cp[4 * NN] + cp[5 * NN];
            float s3 = cp[6 * NN] + cp[7 * NN];
            float colSum = (s0 + s1) + (s2 + s3);
            int jj = tb * NN + j;
            float vo  = g_v[jj];
            float bo  = __expf(vo * inv_eps);
            float lse = __logf(fmaf(bo, colSum, 1e-6f));
            float vn  = EPSF * (log_mu - lse) + vo;
            g_v[jj]  = vn;
            g_bv[jj] = __expf(vn * inv_eps);
        }

        // ===== stop check (identical fixed-order reduction everywhere) =====
        float ev = (tid < GRD) ? g_errPart[tid] : 0.0f;
        #pragma unroll
        for (int o = 16; o; o >>= 1) ev += __shfl_xor_sync(0xffffffffu, ev, o);
        if (lane == 0) shRed[w] = ev;
        __syncthreads();
        float err = (shRed[0] + shRed[1] + shRed[2] + shRed[3]) * (1.0f / BB);
        stop = (err < THRF);
        grid_barrier(target);
    }

    // ===== final: cost = mean_b sum_ij exp((u+v-C)/eps) * C =====
    {
        const float inv_eps2 = 1.0f / EPSF;
        float acc = 0.0f;
        const float4* __restrict__ C4 = (const float4*)g_C;
        const int total4 = BB * NN * NN / 4;
        for (int idx = bid * TPB + tid; idx < total4; idx += GRD * TPB) {
            int row = idx >> 8;
            int j4  = idx & 255;
            int bb  = row >> 10;
            float u = g_u[row];
            float4 c  = C4[idx];
            float4 vv = ((const float4*)(g_v + bb * NN))[j4];
            acc += __expf((u + vv.x - c.x) * inv_eps2) * c.x;
            acc += __expf((u + vv.y - c.y) * inv_eps2) * c.y;
            acc += __expf((u + vv.z - c.z) * inv_eps2) * c.z;
            acc += __expf((u + vv.w - c.w) * inv_eps2) * c.w;
        }
        #pragma unroll
        for (int o = 16; o; o >>= 1) acc += __shfl_xor_sync(0xffffffffu, acc, o);
        if (lane == 0) shRed[w] = acc;
        __syncthreads();
        if (tid == 0) {
            float e = 0.f;
            #pragma unroll
            for (int i = 0; i < 16; i++) e += shRed[i];
            atomicAdd(&g_cost, (double)e);
        }
        grid_barrier(target);
        if (bid == 0 && tid == 0) out[0] = (float)(g_cost * (1.0 / BB));
    }
}

// ---------------- launch ----------------
extern "C" void kernel_launch(void* const* d_in, const int* in_sizes, int n_in,
                              void* d_out, int out_size) {
    const float* x = (const float*)d_in[0];
    const float* y = (const float*)d_in[1];
    float* out = (float*)d_out;

    cudaFuncSetAttribute(sinkhorn_kernel,
                         cudaFuncAttributeMaxDynamicSharedMemorySize,
                         SH_FLOATS * sizeof(float));

    init_kernel<<<64, 256>>>();
    softmax_kernel<<<(2 * BB * NN) / 8, 256>>>(x, y);
    gemm_kernel<<<dim3(8, 8, BB), 256>>>();
    sinkhorn_kernel<<<GRD, TPB, SH_FLOATS * sizeof(float)>>>(out);
}

// round 4
// speedup vs baseline: 3.6401x; 1.6277x over previous
#include <cuda_runtime.h>
#include <cuda_fp16.h>
#include <cuda_bf16.h>
#include <math.h>

// ---------------- problem constants ----------------
#define BB    16
#define NN    1024
#define DD    64
#define EPSF  0.1f
#define MAXIT 100
#define THRF  0.1f
#define GRD   128
#define TPB   512

// ---------------- packed f32x2 helpers ----------------
typedef unsigned long long ull;
__device__ __forceinline__ ull pk2(float lo, float hi) {
    ull r; asm("mov.b64 %0, {%1, %2};" : "=l"(r) : "f"(lo), "f"(hi)); return r;
}
__device__ __forceinline__ void up2(ull v, float& lo, float& hi) {
    asm("mov.b64 {%0, %1}, %2;" : "=f"(lo), "=f"(hi) : "l"(v));
}
#define FMA2(d, a, b) asm("fma.rn.f32x2 %0, %1, %2, %0;" : "+l"(d) : "l"(a), "l"(b))

// ---------------- mma / ldmatrix helpers ----------------
__device__ __forceinline__ void ldsm4(unsigned& r0, unsigned& r1, unsigned& r2,
                                      unsigned& r3, unsigned addr) {
    asm volatile("ldmatrix.sync.aligned.m8n8.x4.shared.b16 {%0,%1,%2,%3}, [%4];"
                 : "=r"(r0), "=r"(r1), "=r"(r2), "=r"(r3) : "r"(addr));
}
__device__ __forceinline__ void mma16816(float* d, const unsigned* a,
                                         unsigned b0, unsigned b1) {
    asm volatile(
        "mma.sync.aligned.m16n8k16.row.col.f32.bf16.bf16.f32 "
        "{%0,%1,%2,%3}, {%4,%5,%6,%7}, {%8,%9}, {%0,%1,%2,%3};"
        : "+f"(d[0]), "+f"(d[1]), "+f"(d[2]), "+f"(d[3])
        : "r"(a[0]), "r"(a[1]), "r"(a[2]), "r"(a[3]), "r"(b0), "r"(b1));
}

// ---------------- device scratch ----------------
__device__ __nv_bfloat16 g_xh[BB * NN * DD];
__device__ __nv_bfloat16 g_xl[BB * NN * DD];
__device__ __nv_bfloat16 g_yh[BB * NN * DD];
__device__ __nv_bfloat16 g_yl[BB * NN * DD];
__device__ float g_x2[BB * NN];
__device__ float g_y2[BB * NN];
__device__ float g_C[(size_t)BB * NN * NN];                 // 64 MB fp32
__device__ __align__(16) __half g_Kh[(size_t)BB * NN * NN]; // 32 MB fp16
__device__ float g_colPart[2][GRD * NN];                    // double-buffered
__device__ float g_errPart[2][GRD];
__device__ double g_cost;
__device__ unsigned g_bar;

// ---------------- init (reset per replay) ----------------
__global__ void init_kernel() {
    if (threadIdx.x == 0) { g_cost = 0.0; g_bar = 0u; }
}

// ---------------- softmax (1 warp per 64-elem row) + bf16 split ----------
__global__ void softmax_kernel(const float* __restrict__ x,
                               const float* __restrict__ y) {
    int w = (blockIdx.x * blockDim.x + threadIdx.x) >> 5;
    int lane = threadIdx.x & 31;
    const float* src; __nv_bfloat16 *dh, *dl; float* nrm; int row;
    if (w < BB * NN) { row = w;           src = x; dh = g_xh; dl = g_xl; nrm = g_x2; }
    else             { row = w - BB * NN; src = y; dh = g_yh; dl = g_yl; nrm = g_y2; }

    const float2* r = (const float2*)(src + (size_t)row * DD);
    float2 v = r[lane];
    float m = fmaxf(v.x, v.y);
    #pragma unroll
    for (int o = 16; o; o >>= 1) m = fmaxf(m, __shfl_xor_sync(0xffffffffu, m, o));
    float e0 = expf(v.x - m), e1 = expf(v.y - m);
    float s = e0 + e1;
    #pragma unroll
    for (int o = 16; o; o >>= 1) s += __shfl_xor_sync(0xffffffffu, s, o);
    float inv = 1.0f / s;
    float p0 = e0 * inv, p1 = e1 * inv;

    __nv_bfloat162 hh, ll;
    hh.x = __float2bfloat16_rn(p0);
    hh.y = __float2bfloat16_rn(p1);
    ll.x = __float2bfloat16_rn(p0 - __bfloat162float(hh.x));
    ll.y = __float2bfloat16_rn(p1 - __bfloat162float(hh.y));
    ((__nv_bfloat162*)(dh + (size_t)row * DD))[lane] = hh;
    ((__nv_bfloat162*)(dl + (size_t)row * DD))[lane] = ll;

    float q = p0 * p0 + p1 * p1;
    #pragma unroll
    for (int o = 16; o; o >>= 1) q += __shfl_xor_sync(0xffffffffu, q, o);
    if (lane == 0) nrm[row] = q;
}

// ---------------- tensor GEMM: C = x2+y2-2XY^T, K = exp(-C/eps) ------------
// block tile 128x128, 8 warps (4 m x 2 n), warp tile 32x64, K=64 whole in smem.
// smem rows padded to 72 halves (144 B) -> ldmatrix conflict-free.
#define ROWP 72
#define TILEH (128 * ROWP)          // halves per tile
__global__ void __launch_bounds__(256) gemm_kernel() {
    extern __shared__ __half sm[];  // [Ah | Al | Bh | Bl], each TILEH halves
    const int b  = blockIdx.z;
    const int i0 = blockIdx.y * 128;
    const int j0 = blockIdx.x * 128;
    const int t  = threadIdx.x;
    const int wid  = t >> 5;
    const int lane = t & 31;
    const int wm = wid & 3;         // m tile 0..3
    const int wn = wid >> 2;        // n tile 0..1

    // ---- load 4 tiles (128 x 64 bf16 each) ----
    {
        const __nv_bfloat16* srcs[4] = {
            g_xh + ((size_t)b * NN + i0) * DD, g_xl + ((size_t)b * NN + i0) * DD,
            g_yh + ((size_t)b * NN + j0) * DD, g_yl + ((size_t)b * NN + j0) * DD };
        #pragma unroll
        for (int ts = 0; ts < 4; ts++) {
            const uint4* s = (const uint4*)srcs[ts];
            #pragma unroll
            for (int q = 0; q < 4; q++) {
                int idx = t + q * 256;          // 0..1023
                int row = idx >> 3, seg = idx & 7;
                uint4 v = s[idx];
                *(uint4*)(sm + ts * TILEH + row * ROWP + seg * 8) = v;
            }
        }
    }
    __syncthreads();

    float acc[2][8][4];
    #pragma unroll
    for (int mt = 0; mt < 2; mt++)
        #pragma unroll
        for (int nt = 0; nt < 8; nt++)
            #pragma unroll
            for (int e = 0; e < 4; e++) acc[mt][nt][e] = 0.0f;

    const unsigned smBase = (unsigned)__cvta_generic_to_shared(sm);
    const int aRowOff = (lane & 7) + (lane & 8);
    const int aColOff = (lane & 16) >> 1;
    const int bRowOff = (lane & 7) + ((lane & 16) >> 1);
    const int bColOff = (lane & 8);

    #pragma unroll
    for (int pass = 0; pass < 3; pass++) {
        const int asel = (pass == 2) ? 1 : 0;   // Al only in pass 2
        const int bsel = (pass == 1) ? 1 : 0;   // Bl only in pass 1
        const unsigned aBase = smBase + asel * TILEH * 2;
        const unsigned bBase = smBase + (2 + bsel) * TILEH * 2;
        #pragma unroll
        for (int ks = 0; ks < 4; ks++) {
            const int kcol = ks * 16;
            unsigned afr[2][4];
            #pragma unroll
            for (int mt = 0; mt < 2; mt++) {
                unsigned addr = aBase +
                    ((wm * 32 + mt * 16 + aRowOff) * ROWP + kcol + aColOff) * 2;
                ldsm4(afr[mt][0], afr[mt][1], afr[mt][2], afr[mt][3], addr);
            }
            unsigned bfr[4][4];
            #pragma unroll
            for (int nq = 0; nq < 4; nq++) {
                unsigned addr = bBase +
                    ((wn * 64 + nq * 16 + bRowOff) * ROWP + kcol + bColOff) * 2;
                ldsm4(bfr[nq][0], bfr[nq][1], bfr[nq][2], bfr[nq][3], addr);
            }
            #pragma unroll
            for (int mt = 0; mt < 2; mt++)
                #pragma unroll
                for (int nq = 0; nq < 4; nq++) {
                    mma16816(acc[mt][2 * nq],     afr[mt], bfr[nq][0], bfr[nq][1]);
                    mma16816(acc[mt][2 * nq + 1], afr[mt], bfr[nq][2], bfr[nq][3]);
                }
        }
    }

    // ---- epilogue: C fp32 + K fp16 ----
    const int g  = lane >> 2;
    const int t4 = lane & 3;
    #pragma unroll
    for (int mt = 0; mt < 2; mt++) {
        #pragma unroll
        for (int hh = 0; hh < 2; hh++) {
            int gi = i0 + wm * 32 + mt * 16 + hh * 8 + g;
            float x2i = g_x2[b * NN + gi];
            size_t rowbase = ((size_t)b * NN + gi) * NN;
            #pragma unroll
            for (int nt = 0; nt < 8; nt++) {
                int gj = j0 + wn * 64 + nt * 8 + t4 * 2;
                float d0 = acc[mt][nt][hh * 2 + 0];
                float d1 = acc[mt][nt][hh * 2 + 1];
                float c0 = x2i + g_y2[b * NN + gj]     - 2.0f * d0;
                float c1 = x2i + g_y2[b * NN + gj + 1] - 2.0f * d1;
                *(float2*)(g_C + rowbase + gj) = make_float2(c0, c1);
                *(__half2*)(g_Kh + rowbase + gj) =
                    __floats2half2_rn(__expf(-10.0f * c0), __expf(-10.0f * c1));
            }
        }
    }
}

// ---------------- software grid barrier ----------------
__device__ __forceinline__ void grid_barrier(unsigned& target) {
    target += GRD;
    __syncthreads();
    if (threadIdx.x == 0) {
        __threadfence();
        atomicAdd(&g_bar, 1u);
        volatile unsigned* p = &g_bar;
        while (*p < target) { __nanosleep(32); }
        __threadfence();
    }
    __syncthreads();
}

// ---------------- persistent Sinkhorn: 1 barrier / iter ----------------------
// smem: shB[1024] | shV[1024] | shU[128] | shCol[16*1026] | shRed[32]
#define COLSTRIDE 1026
#define SH_FLOATS (1024 + 1024 + 128 + 16 * COLSTRIDE + 32)

__global__ void __launch_bounds__(TPB) sinkhorn_kernel(float* __restrict__ out) {
    extern __shared__ float sh[];
    float* shB   = sh;                  // exp(v/eps), this block's batch
    float* shV   = sh + 1024;           // v
    float* shU   = sh + 2048;           // u for owned 128 rows
    float* shCol = sh + 2176;
    float* shRed = shCol + 16 * COLSTRIDE;

    const int tid  = threadIdx.x;
    const int w    = tid >> 5;
    const int lane = tid & 31;
    const int bid  = blockIdx.x;
    const int tb   = bid >> 3;          // batch owned
    unsigned target = 0;
    const float log_mu  = logf(1.0f / NN + 1e-8f);
    const float inv_eps = 1.0f / EPSF;
    bool stop = false;

    for (int i = tid; i < 1024; i += TPB) { shB[i] = 1.0f; shV[i] = 0.0f; }
    if (tid < 128) shU[tid] = 0.0f;
    __syncthreads();

    for (int it = 0; it < MAXIT && !stop; ++it) {
        const int pb = it & 1;
        // ===== fused sweep: u update + column partials, one K pass =====
        ull colAcc[16];
        #pragma unroll
        for (int q = 0; q < 16; q++) colAcc[q] = 0ULL;
        float errAcc = 0.0f;
        const int rowLocalBase = w * 8;

        #pragma unroll 2
        for (int r = 0; r < 8; r++) {
            const int rl  = rowLocalBase + r;
            const int row = bid * 128 + rl;
            const uint4* __restrict__ Kr = (const uint4*)(g_Kh + (size_t)row * NN);
            ull kf[16];
            ull s2 = 0ULL;
            #pragma unroll
            for (int tt = 0; tt < 4; tt++) {
                uint4 q4 = Kr[lane + 32 * tt];
                const __half2* hp = (const __half2*)&q4;
                const ull* bp = (const ull*)(shB + ((lane + 32 * tt) << 3));
                #pragma unroll
                for (int e = 0; e < 4; e++) {
                    float2 f = __half22float2(hp[e]);
                    kf[tt * 4 + e] = pk2(f.x, f.y);
                    FMA2(s2, kf[tt * 4 + e], bp[e]);
                }
            }
            float sx, sy; up2(s2, sx, sy);
            float s = sx + sy;
            #pragma unroll
            for (int o = 16; o; o >>= 1) s += __shfl_xor_sync(0xffffffffu, s, o);

            float uo  = shU[rl];
            float ao  = __expf(uo * inv_eps);
            float lse = __logf(fmaf(ao, s, 1e-6f));
            float un  = EPSF * (log_mu - lse) + uo;
            float an  = __expf(un * inv_eps);
            if (lane == 0) { shU[rl] = un; errAcc += fabsf(un - uo); }
            ull ap = pk2(an, an);
            #pragma unroll
            for (int q = 0; q < 16; q++) FMA2(colAcc[q], ap, kf[q]);
        }

        if (lane == 0) shRed[w] = errAcc;
        {
            float* dst = shCol + w * COLSTRIDE;
            #pragma unroll
            for (int tt = 0; tt < 4; tt++) {
                int jb = (lane + 32 * tt) << 3;
                #pragma unroll
                for (int e = 0; e < 4; e++) {
                    float lo, hi; up2(colAcc[tt * 4 + e], lo, hi);
                    *(float2*)(dst + jb + 2 * e) = make_float2(lo, hi);
                }
            }
        }
        __syncthreads();

        // block column reduce -> global partials (buffer pb)
        #pragma unroll
        for (int half = 0; half < 2; half++) {
            int j = tid + half * TPB;
            float sum = 0.0f;
            #pragma unroll
            for (int ww = 0; ww < 16; ww++) sum += shCol[ww * COLSTRIDE + j];
            g_colPart[pb][bid * NN + j] = sum;
        }
        if (tid == 0) {
            float e = 0.f;
            #pragma unroll
            for (int i = 0; i < 16; i++) e += shRed[i];
            g_errPart[pb][bid] = e;
        }
        grid_barrier(target);

        // ===== local v finalize: sum 8 block partials of own batch =====
        for (int j = tid; j < 1024; j += TPB) {
            const float* cp = g_colPart[pb] + (size_t)(tb * 8) * NN + j;
            float s0 = cp[0 * NN] + cp[1 * NN];
            float s1 = cp[2 * NN] + cp[3 * NN];
            float s2 = cp[4 * NN] + cp[5 * NN];
            float s3 = cp[6 * NN] + cp[7 * NN];
            float colSum = (s0 + s1) + (s2 + s3);
            float vo  = shV[j];
            float bo  = shB[j];
            float lse = __logf(fmaf(bo, colSum, 1e-6f));
            float vn  = EPSF * (log_mu - lse) + vo;
            shV[j] = vn;
            shB[j] = __expf(vn * inv_eps);
        }

        // ===== stop check (same fixed-order reduction in every block) =====
        float ev = (tid < GRD) ? g_errPart[pb][tid] : 0.0f;
        #pragma unroll
        for (int o = 16; o; o >>= 1) ev += __shfl_xor_sync(0xffffffffu, ev, o);
        if (lane == 0) shRed[w] = ev;
        __syncthreads();
        float err = (shRed[0] + shRed[1] + shRed[2] + shRed[3]) * (1.0f / BB);
        stop = (err < THRF);
        __syncthreads();   // protect shRed/shB before next sweep reuses them
    }

    // ===== final: cost partial over owned 128 rows =====
    {
        float acc = 0.0f;
        const float4* __restrict__ C4 =
            (const float4*)(g_C + (size_t)(bid * 128) * NN);
        const int total4 = 128 * NN / 4;
        for (int idx = tid; idx < total4; idx += TPB) {
            int rl = idx >> 8;
            int j4 = idx & 255;
            float u = shU[rl];
            float4 c  = C4[idx];
            float4 vv = ((const float4*)shV)[j4];
            acc += __expf((u + vv.x - c.x) * inv_eps) * c.x;
            acc += __expf((u + vv.y - c.y) * inv_eps) * c.y;
            acc += __expf((u + vv.z - c.z) * inv_eps) * c.z;
            acc += __expf((u + vv.w - c.w) * inv_eps) * c.w;
        }
        #pragma unroll
        for (int o = 16; o; o >>= 1) acc += __shfl_xor_sync(0xffffffffu, acc, o);
        if (lane == 0) shRed[w] = acc;
        __syncthreads();
        if (tid == 0) {
            float e = 0.f;
            #pragma unroll
            for (int i = 0; i < 16; i++) e += shRed[i];
            atomicAdd(&g_cost, (double)e);
        }
        grid_barrier(target);
        if (bid == 0 && tid == 0) out[0] = (float)(g_cost * (1.0 / BB));
    }
}

// ---------------- launch ----------------
extern "C" void kernel_launch(void* const* d_in, const int* in_sizes, int n_in,
                              void* d_out, int out_size) {
    const float* x = (const float*)d_in[0];
    const float* y = (const float*)d_in[1];
    float* out = (float*)d_out;

    static int attrDone = 0;
    if (!attrDone) {
        cudaFuncSetAttribute(gemm_kernel,
                             cudaFuncAttributeMaxDynamicSharedMemorySize,
                             4 * TILEH * sizeof(__half));
        cudaFuncSetAttribute(sinkhorn_kernel,
                             cudaFuncAttributeMaxDynamicSharedMemorySize,
                             SH_FLOATS * sizeof(float));
        attrDone = 1;
    }

    init_kernel<<<1, 32>>>();
    softmax_kernel<<<(2 * BB * NN) / 8, 256>>>(x, y);
    gemm_kernel<<<dim3(8, 8, BB), 256, 4 * TILEH * sizeof(__half)>>>();
    sinkhorn_kernel<<<GRD, TPB, SH_FLOATS * sizeof(float)>>>(out);
}

// round 5
// speedup vs baseline: 4.2106x; 1.1567x over previous
#include <cuda_runtime.h>
#include <cuda_fp16.h>
#include <cuda_bf16.h>
#include <math.h>

// ---------------- problem constants ----------------
#define BB    16
#define NN    1024
#define DD    64
#define EPSF  0.1f
#define MAXIT 100
#define THRF  0.1f
#define GRD   128
#define TPB   512

// ---------------- packed f32x2 helpers ----------------
typedef unsigned long long ull;
__device__ __forceinline__ ull pk2(float lo, float hi) {
    ull r; asm("mov.b64 %0, {%1, %2};" : "=l"(r) : "f"(lo), "f"(hi)); return r;
}
__device__ __forceinline__ void up2(ull v, float& lo, float& hi) {
    asm("mov.b64 {%0, %1}, %2;" : "=f"(lo), "=f"(hi) : "l"(v));
}
#define FMA2(d, a, b) asm("fma.rn.f32x2 %0, %1, %2, %0;" : "+l"(d) : "l"(a), "l"(b))
#define MUL2(d, a, b) asm("mul.rn.f32x2 %0, %1, %2;" : "=l"(d) : "l"(a), "l"(b))

// ---------------- mma / ldmatrix helpers ----------------
__device__ __forceinline__ void ldsm4(unsigned& r0, unsigned& r1, unsigned& r2,
                                      unsigned& r3, unsigned addr) {
    asm volatile("ldmatrix.sync.aligned.m8n8.x4.shared.b16 {%0,%1,%2,%3}, [%4];"
                 : "=r"(r0), "=r"(r1), "=r"(r2), "=r"(r3) : "r"(addr));
}
__device__ __forceinline__ void mma16816(float* d, const unsigned* a,
                                         unsigned b0, unsigned b1) {
    asm volatile(
        "mma.sync.aligned.m16n8k16.row.col.f32.bf16.bf16.f32 "
        "{%0,%1,%2,%3}, {%4,%5,%6,%7}, {%8,%9}, {%0,%1,%2,%3};"
        : "+f"(d[0]), "+f"(d[1]), "+f"(d[2]), "+f"(d[3])
        : "r"(a[0]), "r"(a[1]), "r"(a[2]), "r"(a[3]), "r"(b0), "r"(b1));
}

// ---------------- device scratch ----------------
__device__ __nv_bfloat16 g_xh[BB * NN * DD];
__device__ __nv_bfloat16 g_xl[BB * NN * DD];
__device__ __nv_bfloat16 g_yh[BB * NN * DD];
__device__ __nv_bfloat16 g_yl[BB * NN * DD];
__device__ float g_x2[BB * NN];
__device__ float g_y2[BB * NN];
__device__ __align__(16) __half g_Ch[(size_t)BB * NN * NN]; // 32 MB fp16 cost
__device__ __align__(16) __half g_Kh[(size_t)BB * NN * NN]; // 32 MB fp16 kernel
__device__ float g_colPart[2][GRD * NN];                    // double-buffered
__device__ float g_errPart[2][GRD];
__device__ double g_cost;
__device__ unsigned g_bar;

// ---------------- softmax (1 warp / 64-elem row) + bf16 split + init -------
__global__ void softmax_kernel(const float* __restrict__ x,
                               const float* __restrict__ y) {
    if (blockIdx.x == 0 && threadIdx.x == 0) { g_cost = 0.0; g_bar = 0u; }
    int w = (blockIdx.x * blockDim.x + threadIdx.x) >> 5;
    int lane = threadIdx.x & 31;
    const float* src; __nv_bfloat16 *dh, *dl; float* nrm; int row;
    if (w < BB * NN) { row = w;           src = x; dh = g_xh; dl = g_xl; nrm = g_x2; }
    else             { row = w - BB * NN; src = y; dh = g_yh; dl = g_yl; nrm = g_y2; }

    const float2* r = (const float2*)(src + (size_t)row * DD);
    float2 v = r[lane];
    float m = fmaxf(v.x, v.y);
    #pragma unroll
    for (int o = 16; o; o >>= 1) m = fmaxf(m, __shfl_xor_sync(0xffffffffu, m, o));
    float e0 = expf(v.x - m), e1 = expf(v.y - m);
    float s = e0 + e1;
    #pragma unroll
    for (int o = 16; o; o >>= 1) s += __shfl_xor_sync(0xffffffffu, s, o);
    float inv = 1.0f / s;
    float p0 = e0 * inv, p1 = e1 * inv;

    __nv_bfloat162 hh, ll;
    hh.x = __float2bfloat16_rn(p0);
    hh.y = __float2bfloat16_rn(p1);
    ll.x = __float2bfloat16_rn(p0 - __bfloat162float(hh.x));
    ll.y = __float2bfloat16_rn(p1 - __bfloat162float(hh.y));
    ((__nv_bfloat162*)(dh + (size_t)row * DD))[lane] = hh;
    ((__nv_bfloat162*)(dl + (size_t)row * DD))[lane] = ll;

    float q = p0 * p0 + p1 * p1;
    #pragma unroll
    for (int o = 16; o; o >>= 1) q += __shfl_xor_sync(0xffffffffu, q, o);
    if (lane == 0) nrm[row] = q;
}

// ---------------- tensor GEMM: C = x2+y2-2XY^T (fp16), K = exp(-C/eps) -----
#define ROWP 72
#define TILEH (128 * ROWP)          // halves per tile
__global__ void __launch_bounds__(256) gemm_kernel() {
    extern __shared__ __half sm[];  // [Ah | Al | Bh | Bl], each TILEH halves
    const int b  = blockIdx.z;
    const int i0 = blockIdx.y * 128;
    const int j0 = blockIdx.x * 128;
    const int t  = threadIdx.x;
    const int wid  = t >> 5;
    const int lane = t & 31;
    const int wm = wid & 3;
    const int wn = wid >> 2;

    {
        const __nv_bfloat16* srcs[4] = {
            g_xh + ((size_t)b * NN + i0) * DD, g_xl + ((size_t)b * NN + i0) * DD,
            g_yh + ((size_t)b * NN + j0) * DD, g_yl + ((size_t)b * NN + j0) * DD };
        #pragma unroll
        for (int ts = 0; ts < 4; ts++) {
            const uint4* s = (const uint4*)srcs[ts];
            #pragma unroll
            for (int q = 0; q < 4; q++) {
                int idx = t + q * 256;
                int row = idx >> 3, seg = idx & 7;
                uint4 v = s[idx];
                *(uint4*)(sm + ts * TILEH + row * ROWP + seg * 8) = v;
            }
        }
    }
    __syncthreads();

    float acc[2][8][4];
    #pragma unroll
    for (int mt = 0; mt < 2; mt++)
        #pragma unroll
        for (int nt = 0; nt < 8; nt++)
            #pragma unroll
            for (int e = 0; e < 4; e++) acc[mt][nt][e] = 0.0f;

    const unsigned smBase = (unsigned)__cvta_generic_to_shared(sm);
    const int aRowOff = (lane & 7) + (lane & 8);
    const int aColOff = (lane & 16) >> 1;
    const int bRowOff = (lane & 7) + ((lane & 16) >> 1);
    const int bColOff = (lane & 8);

    #pragma unroll
    for (int pass = 0; pass < 3; pass++) {
        const int asel = (pass == 2) ? 1 : 0;
        const int bsel = (pass == 1) ? 1 : 0;
        const unsigned aBase = smBase + asel * TILEH * 2;
        const unsigned bBase = smBase + (2 + bsel) * TILEH * 2;
        #pragma unroll
        for (int ks = 0; ks < 4; ks++) {
            const int kcol = ks * 16;
            unsigned afr[2][4];
            #pragma unroll
            for (int mt = 0; mt < 2; mt++) {
                unsigned addr = aBase +
                    ((wm * 32 + mt * 16 + aRowOff) * ROWP + kcol + aColOff) * 2;
                ldsm4(afr[mt][0], afr[mt][1], afr[mt][2], afr[mt][3], addr);
            }
            unsigned bfr[4][4];
            #pragma unroll
            for (int nq = 0; nq < 4; nq++) {
                unsigned addr = bBase +
                    ((wn * 64 + nq * 16 + bRowOff) * ROWP + kcol + bColOff) * 2;
                ldsm4(bfr[nq][0], bfr[nq][1], bfr[nq][2], bfr[nq][3], addr);
            }
            #pragma unroll
            for (int mt = 0; mt < 2; mt++)
                #pragma unroll
                for (int nq = 0; nq < 4; nq++) {
                    mma16816(acc[mt][2 * nq],     afr[mt], bfr[nq][0], bfr[nq][1]);
                    mma16816(acc[mt][2 * nq + 1], afr[mt], bfr[nq][2], bfr[nq][3]);
                }
        }
    }

    // ---- epilogue: C fp16 + K fp16 ----
    const int g  = lane >> 2;
    const int t4 = lane & 3;
    float y2v[16];
    #pragma unroll
    for (int nt = 0; nt < 8; nt++) {
        int gj = j0 + wn * 64 + nt * 8 + t4 * 2;
        y2v[2 * nt]     = g_y2[b * NN + gj];
        y2v[2 * nt + 1] = g_y2[b * NN + gj + 1];
    }
    #pragma unroll
    for (int mt = 0; mt < 2; mt++) {
        #pragma unroll
        for (int hh = 0; hh < 2; hh++) {
            int gi = i0 + wm * 32 + mt * 16 + hh * 8 + g;
            float x2i = g_x2[b * NN + gi];
            size_t rowbase = ((size_t)b * NN + gi) * NN;
            #pragma unroll
            for (int nt = 0; nt < 8; nt++) {
                int gj = j0 + wn * 64 + nt * 8 + t4 * 2;
                float d0 = acc[mt][nt][hh * 2 + 0];
                float d1 = acc[mt][nt][hh * 2 + 1];
                float c0 = x2i + y2v[2 * nt]     - 2.0f * d0;
                float c1 = x2i + y2v[2 * nt + 1] - 2.0f * d1;
                *(__half2*)(g_Ch + rowbase + gj) = __floats2half2_rn(c0, c1);
                *(__half2*)(g_Kh + rowbase + gj) =
                    __floats2half2_rn(__expf(-10.0f * c0), __expf(-10.0f * c1));
            }
        }
    }
}

// ---------------- software grid barrier ----------------
__device__ __forceinline__ void grid_barrier(unsigned& target) {
    target += GRD;
    __syncthreads();
    if (threadIdx.x == 0) {
        __threadfence();
        atomicAdd(&g_bar, 1u);
        volatile unsigned* p = &g_bar;
        while (*p < target) { __nanosleep(32); }
        __threadfence();
    }
    __syncthreads();
}

// ---------------- persistent Sinkhorn: 1 barrier / iter ----------------------
#define COLSTRIDE 1026
#define SH_FLOATS (1024 + 1024 + 128 + 16 * COLSTRIDE + 32)

__global__ void __launch_bounds__(TPB) sinkhorn_kernel(float* __restrict__ out) {
    extern __shared__ float sh[];
    float* shB   = sh;                  // exp(v/eps)
    float* shV   = sh + 1024;           // v
    float* shU   = sh + 2048;           // u (owned 128 rows)
    float* shCol = sh + 2176;
    float* shRed = shCol + 16 * COLSTRIDE;

    const int tid  = threadIdx.x;
    const int w    = tid >> 5;
    const int lane = tid & 31;
    const int bid  = blockIdx.x;
    const int tb   = bid >> 3;
    unsigned target = 0;
    const float log_mu  = logf(1.0f / NN + 1e-8f);
    const float inv_eps = 1.0f / EPSF;
    bool stop = false;

    for (int i = tid; i < 1024; i += TPB) { shB[i] = 1.0f; shV[i] = 0.0f; }
    if (tid < 128) shU[tid] = 0.0f;
    __syncthreads();

    for (int it = 0; it < MAXIT && !stop; ++it) {
        const int pb = it & 1;
        ull colAcc[16];
        #pragma unroll
        for (int q = 0; q < 16; q++) colAcc[q] = 0ULL;
        float errAcc = 0.0f;
        const int rowLocalBase = w * 8;

        #pragma unroll 2
        for (int r = 0; r < 8; r++) {
            const int rl  = rowLocalBase + r;
            const int row = bid * 128 + rl;
            const uint4* __restrict__ Kr = (const uint4*)(g_Kh + (size_t)row * NN);
            ull kf[16];
            ull s2 = 0ULL;
            #pragma unroll
            for (int tt = 0; tt < 4; tt++) {
                uint4 q4 = Kr[lane + 32 * tt];
                const __half2* hp = (const __half2*)&q4;
                const ull* bp = (const ull*)(shB + ((lane + 32 * tt) << 3));
                #pragma unroll
                for (int e = 0; e < 4; e++) {
                    float2 f = __half22float2(hp[e]);
                    kf[tt * 4 + e] = pk2(f.x, f.y);
                    FMA2(s2, kf[tt * 4 + e], bp[e]);
                }
            }
            float sx, sy; up2(s2, sx, sy);
            float s = sx + sy;
            #pragma unroll
            for (int o = 16; o; o >>= 1) s += __shfl_xor_sync(0xffffffffu, s, o);

            float uo  = shU[rl];
            float ao  = __expf(uo * inv_eps);
            float lse = __logf(fmaf(ao, s, 1e-6f));
            float un  = EPSF * (log_mu - lse) + uo;
            float an  = __expf(un * inv_eps);
            if (lane == 0) { shU[rl] = un; errAcc += fabsf(un - uo); }
            ull ap = pk2(an, an);
            #pragma unroll
            for (int q = 0; q < 16; q++) FMA2(colAcc[q], ap, kf[q]);
        }

        if (lane == 0) shRed[w] = errAcc;
        {
            float* dst = shCol + w * COLSTRIDE;
            #pragma unroll
            for (int tt = 0; tt < 4; tt++) {
                int jb = (lane + 32 * tt) << 3;
                #pragma unroll
                for (int e = 0; e < 4; e++) {
                    float lo, hi; up2(colAcc[tt * 4 + e], lo, hi);
                    *(float2*)(dst + jb + 2 * e) = make_float2(lo, hi);
                }
            }
        }
        __syncthreads();

        #pragma unroll
        for (int half = 0; half < 2; half++) {
            int j = tid + half * TPB;
            float sum = 0.0f;
            #pragma unroll
            for (int ww = 0; ww < 16; ww++) sum += shCol[ww * COLSTRIDE + j];
            g_colPart[pb][bid * NN + j] = sum;
        }
        if (tid == 0) {
            float e = 0.f;
            #pragma unroll
            for (int i = 0; i < 16; i++) e += shRed[i];
            g_errPart[pb][bid] = e;
        }
        grid_barrier(target);

        for (int j = tid; j < 1024; j += TPB) {
            const float* cp = g_colPart[pb] + (size_t)(tb * 8) * NN + j;
            float s0 = cp[0 * NN] + cp[1 * NN];
            float s1 = cp[2 * NN] + cp[3 * NN];
            float s2 = cp[4 * NN] + cp[5 * NN];
            float s3 = cp[6 * NN] + cp[7 * NN];
            float colSum = (s0 + s1) + (s2 + s3);
            float vo  = shV[j];
            float bo  = shB[j];
            float lse = __logf(fmaf(bo, colSum, 1e-6f));
            float vn  = EPSF * (log_mu - lse) + vo;
            shV[j] = vn;
            shB[j] = __expf(vn * inv_eps);
        }

        float ev = (tid < GRD) ? g_errPart[pb][tid] : 0.0f;
        #pragma unroll
        for (int o = 16; o; o >>= 1) ev += __shfl_xor_sync(0xffffffffu, ev, o);
        if (lane == 0) shRed[w] = ev;
        __syncthreads();
        float err = (shRed[0] + shRed[1] + shRed[2] + shRed[3]) * (1.0f / BB);
        stop = (err < THRF);
        __syncthreads();
    }

    // ===== final: cost = sum_ij a_i * K_ij * b_j * C_ij  (no exp, fp16 reads)
    // Only own-block data -> no barrier needed before this section.
    {
        float acc = 0.0f;
        const int rowLocalBase = w * 8;
        #pragma unroll 2
        for (int r = 0; r < 8; r++) {
            const int rl  = rowLocalBase + r;
            const int row = bid * 128 + rl;
            const uint4* __restrict__ Kr = (const uint4*)(g_Kh + (size_t)row * NN);
            const uint4* __restrict__ Cr = (const uint4*)(g_Ch + (size_t)row * NN);
            ull s2 = 0ULL;
            #pragma unroll
            for (int tt = 0; tt < 4; tt++) {
                uint4 kq = Kr[lane + 32 * tt];
                uint4 cq = Cr[lane + 32 * tt];
                const __half2* kp = (const __half2*)&kq;
                const __half2* cp = (const __half2*)&cq;
                const ull* bp = (const ull*)(shB + ((lane + 32 * tt) << 3));
                #pragma unroll
                for (int e = 0; e < 4; e++) {
                    float2 kf = __half22float2(kp[e]);
                    float2 cf = __half22float2(cp[e]);
                    ull kb;
                    MUL2(kb, pk2(kf.x, kf.y), bp[e]);       // K * b
                    FMA2(s2, kb, pk2(cf.x, cf.y));          // += (K*b) * C
                }
            }
            float sx, sy; up2(s2, sx, sy);
            float s = sx + sy;
            #pragma unroll
            for (int o = 16; o; o >>= 1) s += __shfl_xor_sync(0xffffffffu, s, o);
            if (lane == 0) acc += __expf(shU[rl] * inv_eps) * s;
        }
        if (lane == 0) shRed[w] = acc;
        __syncthreads();
        if (tid == 0) {
            float e = 0.f;
            #pragma unroll
            for (int i = 0; i < 16; i++) e += shRed[i];
            atomicAdd(&g_cost, (double)e);
        }
        grid_barrier(target);
        if (bid == 0 && tid == 0) out[0] = (float)(g_cost * (1.0 / BB));
    }
}

// ---------------- launch ----------------
extern "C" void kernel_launch(void* const* d_in, const int* in_sizes, int n_in,
                              void* d_out, int out_size) {
    const float* x = (const float*)d_in[0];
    const float* y = (const float*)d_in[1];
    float* out = (float*)d_out;

    static int attrDone = 0;
    if (!attrDone) {
        cudaFuncSetAttribute(gemm_kernel,
                             cudaFuncAttributeMaxDynamicSharedMemorySize,
                             4 * TILEH * sizeof(__half));
        cudaFuncSetAttribute(sinkhorn_kernel,
                             cudaFuncAttributeMaxDynamicSharedMemorySize,
                             SH_FLOATS * sizeof(float));
        attrDone = 1;
    }

    softmax_kernel<<<(2 * BB * NN) / 8, 256>>>(x, y);
    gemm_kernel<<<dim3(8, 8, BB), 256, 4 * TILEH * sizeof(__half)>>>();
    sinkhorn_kernel<<<GRD, TPB, SH_FLOATS * sizeof(float)>>>(out);
}

// round 7
// speedup vs baseline: 4.5764x; 1.0869x over previous
#include <cuda_runtime.h>
#include <cuda_fp16.h>
#include <cuda_bf16.h>
#include <math.h>

// ---------------- problem constants ----------------
#define BB    16
#define NN    1024
#define DD    64
#define EPSF  0.1f
#define MAXIT 100
#define THRF  0.1f
#define GRD   128
#define TPB   512

// ---------------- packed f32x2 helpers ----------------
typedef unsigned long long ull;
__device__ __forceinline__ ull pk2(float lo, float hi) {
    ull r; asm("mov.b64 %0, {%1, %2};" : "=l"(r) : "f"(lo), "f"(hi)); return r;
}
__device__ __forceinline__ void up2(ull v, float& lo, float& hi) {
    asm("mov.b64 {%0, %1}, %2;" : "=f"(lo), "=f"(hi) : "l"(v));
}
#define FMA2(d, a, b) asm("fma.rn.f32x2 %0, %1, %2, %0;" : "+l"(d) : "l"(a), "l"(b))
#define MUL2(d, a, b) asm("mul.rn.f32x2 %0, %1, %2;" : "=l"(d) : "l"(a), "l"(b))

// butterfly-shuffle reductions
__device__ __forceinline__ float warp_sum(float v) {
    #pragma unroll
    for (int o = 16; o; o >>= 1) v += __shfl_xor_sync(0xffffffffu, v, o);
    return v;
}
__device__ __forceinline__ float seg8_sum(float v) {     // 8-lane segments
    v += __shfl_xor_sync(0xffffffffu, v, 1);
    v += __shfl_xor_sync(0xffffffffu, v, 2);
    v += __shfl_xor_sync(0xffffffffu, v, 4);
    return v;
}

// ---------------- mma / ldmatrix helpers ----------------
__device__ __forceinline__ void ldsm4(unsigned& r0, unsigned& r1, unsigned& r2,
                                      unsigned& r3, unsigned addr) {
    asm volatile("ldmatrix.sync.aligned.m8n8.x4.shared.b16 {%0,%1,%2,%3}, [%4];"
                 : "=r"(r0), "=r"(r1), "=r"(r2), "=r"(r3) : "r"(addr));
}
__device__ __forceinline__ void mma16816(float* d, const unsigned* a,
                                         unsigned b0, unsigned b1) {
    asm volatile(
        "mma.sync.aligned.m16n8k16.row.col.f32.bf16.bf16.f32 "
        "{%0,%1,%2,%3}, {%4,%5,%6,%7}, {%8,%9}, {%0,%1,%2,%3};"
        : "+f"(d[0]), "+f"(d[1]), "+f"(d[2]), "+f"(d[3])
        : "r"(a[0]), "r"(a[1]), "r"(a[2]), "r"(a[3]), "r"(b0), "r"(b1));
}

// ---------------- device scratch ----------------
__device__ __nv_bfloat16 g_xh[BB * NN * DD];
__device__ __nv_bfloat16 g_xl[BB * NN * DD];
__device__ __nv_bfloat16 g_yh[BB * NN * DD];
__device__ __nv_bfloat16 g_yl[BB * NN * DD];
__device__ float g_x2[BB * NN];
__device__ float g_y2[BB * NN];
__device__ __align__(16) __half g_Ch[(size_t)BB * NN * NN]; // 32 MB fp16 cost
__device__ __align__(16) __half g_Kh[(size_t)BB * NN * NN]; // 32 MB fp16 kernel
__device__ float g_colPart[2][GRD * NN];
__device__ float g_errPart[2][GRD];
__device__ double g_cost;
__device__ unsigned g_bar;

// ---------------- softmax: 8 threads/row, no-max, seg8 shuffles -------------
__global__ void __launch_bounds__(256) softmax_kernel(const float* __restrict__ x,
                                                      const float* __restrict__ y) {
    if (blockIdx.x == 0 && threadIdx.x == 0) { g_cost = 0.0; g_bar = 0u; }
    int t  = blockIdx.x * blockDim.x + threadIdx.x;
    int g  = t >> 3;               // row id over both tensors
    int lg = t & 7;
    const float* src; __nv_bfloat16 *dh, *dl; float* nrm; int row;
    if (g < BB * NN) { row = g;           src = x; dh = g_xh; dl = g_xl; nrm = g_x2; }
    else             { row = g - BB * NN; src = y; dh = g_yh; dl = g_yl; nrm = g_y2; }

    const float4* r = (const float4*)(src + (size_t)row * DD);
    float4 v0 = r[lg * 2], v1 = r[lg * 2 + 1];
    float e[8] = {__expf(v0.x), __expf(v0.y), __expf(v0.z), __expf(v0.w),
                  __expf(v1.x), __expf(v1.y), __expf(v1.z), __expf(v1.w)};
    float s = ((e[0] + e[1]) + (e[2] + e[3])) + ((e[4] + e[5]) + (e[6] + e[7]));
    s = seg8_sum(s);
    float inv = 1.0f / s;

    float p[8]; float q = 0.0f;
    #pragma unroll
    for (int k = 0; k < 8; k++) { p[k] = e[k] * inv; q += p[k] * p[k]; }

    union { __nv_bfloat162 h2[4]; uint4 u; } hh, ll;
    #pragma unroll
    for (int k = 0; k < 4; k++) {
        __nv_bfloat16 h0 = __float2bfloat16_rn(p[2 * k]);
        __nv_bfloat16 h1 = __float2bfloat16_rn(p[2 * k + 1]);
        hh.h2[k].x = h0; hh.h2[k].y = h1;
        ll.h2[k].x = __float2bfloat16_rn(p[2 * k]     - __bfloat162float(h0));
        ll.h2[k].y = __float2bfloat16_rn(p[2 * k + 1] - __bfloat162float(h1));
    }
    *(uint4*)(dh + (size_t)row * DD + lg * 8) = hh.u;
    *(uint4*)(dl + (size_t)row * DD + lg * 8) = ll.u;

    q = seg8_sum(q);
    if (lg == 0) nrm[row] = q;
}

// ---------------- tensor GEMM: C = x2+y2-2XY^T (fp16), K = exp(-C/eps) -----
#define ROWP 72
#define TILEH (128 * ROWP)          // halves per tile
#define EPIST 136                   // epilogue smem stride (conflict-free)
__global__ void __launch_bounds__(256) gemm_kernel() {
    extern __shared__ __half sm[];  // compute: [Ah|Al|Bh|Bl]; epilogue: [C|K]
    const int b  = blockIdx.z;
    const int i0 = blockIdx.y * 128;
    const int j0 = blockIdx.x * 128;
    const int t  = threadIdx.x;
    const int wid  = t >> 5;
    const int lane = t & 31;
    const int wm = wid & 3;
    const int wn = wid >> 2;

    {
        const __nv_bfloat16* srcs[4] = {
            g_xh + ((size_t)b * NN + i0) * DD, g_xl + ((size_t)b * NN + i0) * DD,
            g_yh + ((size_t)b * NN + j0) * DD, g_yl + ((size_t)b * NN + j0) * DD };
        #pragma unroll
        for (int ts = 0; ts < 4; ts++) {
            const uint4* s = (const uint4*)srcs[ts];
            #pragma unroll
            for (int q = 0; q < 4; q++) {
                int idx = t + q * 256;
                int row = idx >> 3, seg = idx & 7;
                uint4 v = s[idx];
                *(uint4*)(sm + ts * TILEH + row * ROWP + seg * 8) = v;
            }
        }
    }
    __syncthreads();

    float acc[2][8][4];
    #pragma unroll
    for (int mt = 0; mt < 2; mt++)
        #pragma unroll
        for (int nt = 0; nt < 8; nt++)
            #pragma unroll
            for (int e = 0; e < 4; e++) acc[mt][nt][e] = 0.0f;

    const unsigned smBase = (unsigned)__cvta_generic_to_shared(sm);
    const int aRowOff = (lane & 7) + (lane & 8);
    const int aColOff = (lane & 16) >> 1;
    const int bRowOff = (lane & 7) + ((lane & 16) >> 1);
    const int bColOff = (lane & 8);

    #pragma unroll
    for (int pass = 0; pass < 3; pass++) {
        const int asel = (pass == 2) ? 1 : 0;
        const int bsel = (pass == 1) ? 1 : 0;
        const unsigned aBase = smBase + asel * TILEH * 2;
        const unsigned bBase = smBase + (2 + bsel) * TILEH * 2;
        #pragma unroll
        for (int ks = 0; ks < 4; ks++) {
            const int kcol = ks * 16;
            unsigned afr[2][4];
            #pragma unroll
            for (int mt = 0; mt < 2; mt++) {
                unsigned addr = aBase +
                    ((wm * 32 + mt * 16 + aRowOff) * ROWP + kcol + aColOff) * 2;
                ldsm4(afr[mt][0], afr[mt][1], afr[mt][2], afr[mt][3], addr);
            }
            unsigned bfr[4][4];
            #pragma unroll
            for (int nq = 0; nq < 4; nq++) {
                unsigned addr = bBase +
                    ((wn * 64 + nq * 16 + bRowOff) * ROWP + kcol + bColOff) * 2;
                ldsm4(bfr[nq][0], bfr[nq][1], bfr[nq][2], bfr[nq][3], addr);
            }
            #pragma unroll
            for (int mt = 0; mt < 2; mt++)
                #pragma unroll
                for (int nq = 0; nq < 4; nq++) {
                    mma16816(acc[mt][2 * nq],     afr[mt], bfr[nq][0], bfr[nq][1]);
                    mma16816(acc[mt][2 * nq + 1], afr[mt], bfr[nq][2], bfr[nq][3]);
                }
        }
    }

    // ---- epilogue: stage C/K through smem, coalesced 128B stores ----
    const int g  = lane >> 2;
    const int t4 = lane & 3;
    float y2v[16];
    #pragma unroll
    for (int nt = 0; nt < 8; nt++) {
        int gj = j0 + wn * 64 + nt * 8 + t4 * 2;
        y2v[2 * nt]     = g_y2[b * NN + gj];
        y2v[2 * nt + 1] = g_y2[b * NN + gj + 1];
    }
    __syncthreads();                       // tiles no longer needed
    __half* smC = sm;
    __half* smK = sm + 128 * EPIST;
    #pragma unroll
    for (int mt = 0; mt < 2; mt++) {
        #pragma unroll
        for (int hh = 0; hh < 2; hh++) {
            int lrow = wm * 32 + mt * 16 + hh * 8 + g;
            float x2i = g_x2[b * NN + i0 + lrow];
            #pragma unroll
            for (int nt = 0; nt < 8; nt++) {
                int lcol = wn * 64 + nt * 8 + t4 * 2;
                float d0 = acc[mt][nt][hh * 2 + 0];
                float d1 = acc[mt][nt][hh * 2 + 1];
                float c0 = x2i + y2v[2 * nt]     - 2.0f * d0;
                float c1 = x2i + y2v[2 * nt + 1] - 2.0f * d1;
                *(__half2*)(smC + lrow * EPIST + lcol) = __floats2half2_rn(c0, c1);
                *(__half2*)(smK + lrow * EPIST + lcol) =
                    __floats2half2_rn(__expf(-10.0f * c0), __expf(-10.0f * c1));
            }
        }
    }
    __syncthreads();
    {
        const __half* sarr[2] = {smC, smK};
        __half* darr[2] = {g_Ch, g_Kh};
        #pragma unroll
        for (int a = 0; a < 2; a++) {
            #pragma unroll
            for (int q = 0; q < 8; q++) {
                int idx = q * 256 + t;          // 0..2047
                int row = idx >> 4, seg = idx & 15;
                uint4 v = *(const uint4*)(sarr[a] + row * EPIST + seg * 8);
                *(uint4*)(darr[a] + ((size_t)b * NN + i0 + row) * NN + j0 + seg * 8) = v;
            }
        }
    }
}

// ---------------- software grid barrier ----------------
__device__ __forceinline__ void grid_barrier(unsigned& target) {
    target += GRD;
    __syncthreads();
    if (threadIdx.x == 0) {
        __threadfence();
        atomicAdd(&g_bar, 1u);
        volatile unsigned* p = &g_bar;
        while (*p < target) { __nanosleep(32); }
        __threadfence();
    }
    __syncthreads();
}

// ---------------- persistent Sinkhorn: 1 barrier / iter ----------------------
#define COLSTRIDE 1026
#define SH_FLOATS (1024 + 1024 + 128 + 16 * COLSTRIDE + 32)

__global__ void __launch_bounds__(TPB) sinkhorn_kernel(float* __restrict__ out) {
    extern __shared__ float sh[];
    float* shB   = sh;                  // exp(v/eps)
    float* shV   = sh + 1024;           // v
    float* shU   = sh + 2048;           // u (owned 128 rows)
    float* shCol = sh + 2176;
    float* shRed = shCol + 16 * COLSTRIDE;

    const int tid  = threadIdx.x;
    const int w    = tid >> 5;
    const int lane = tid & 31;
    const int bid  = blockIdx.x;
    const int tb   = bid >> 3;
    unsigned target = 0;
    const float log_mu  = logf(1.0f / NN + 1e-8f);
    const float inv_eps = 1.0f / EPSF;
    bool stop = false;

    for (int i = tid; i < 1024; i += TPB) { shB[i] = 1.0f; shV[i] = 0.0f; }
    if (tid < 128) shU[tid] = 0.0f;
    __syncthreads();

    for (int it = 0; it < MAXIT && !stop; ++it) {
        const int pb = it & 1;
        ull colAcc[16];
        #pragma unroll
        for (int q = 0; q < 16; q++) colAcc[q] = 0ULL;
        float errAcc = 0.0f;
        const int rowLocalBase = w * 8;

        #pragma unroll 2
        for (int r = 0; r < 8; r++) {
            const int rl  = rowLocalBase + r;
            const int row = bid * 128 + rl;
            const uint4* __restrict__ Kr = (const uint4*)(g_Kh + (size_t)row * NN);
            ull kf[16];
            ull s2 = 0ULL;
            #pragma unroll
            for (int tt = 0; tt < 4; tt++) {
                uint4 q4 = Kr[lane + 32 * tt];
                const __half2* hp = (const __half2*)&q4;
                const ull* bp = (const ull*)(shB + ((lane + 32 * tt) << 3));
                #pragma unroll
                for (int e = 0; e < 4; e++) {
                    float2 f = __half22float2(hp[e]);
                    kf[tt * 4 + e] = pk2(f.x, f.y);
                    FMA2(s2, kf[tt * 4 + e], bp[e]);
                }
            }
            float sx, sy; up2(s2, sx, sy);
            float s = warp_sum(sx + sy);

            float uo  = shU[rl];
            float ao  = __expf(uo * inv_eps);
            float lse = __logf(fmaf(ao, s, 1e-6f));
            float un  = EPSF * (log_mu - lse) + uo;
            float an  = __expf(un * inv_eps);
            if (lane == 0) { shU[rl] = un; errAcc += fabsf(un - uo); }
            ull ap = pk2(an, an);
            #pragma unroll
            for (int q = 0; q < 16; q++) FMA2(colAcc[q], ap, kf[q]);
        }

        if (lane == 0) shRed[w] = errAcc;
        {
            float* dst = shCol + w * COLSTRIDE;
            #pragma unroll
            for (int tt = 0; tt < 4; tt++) {
                int jb = (lane + 32 * tt) << 3;
                #pragma unroll
                for (int e = 0; e < 4; e++) {
                    float lo, hi; up2(colAcc[tt * 4 + e], lo, hi);
                    *(float2*)(dst + jb + 2 * e) = make_float2(lo, hi);
                }
            }
        }
        __syncthreads();

        #pragma unroll
        for (int half = 0; half < 2; half++) {
            int j = tid + half * TPB;
            float sum = 0.0f;
            #pragma unroll
            for (int ww = 0; ww < 16; ww++) sum += shCol[ww * COLSTRIDE + j];
            g_colPart[pb][bid * NN + j] = sum;
        }
        if (tid == 0) {
            float e = 0.f;
            #pragma unroll
            for (int i = 0; i < 16; i++) e += shRed[i];
            g_errPart[pb][bid] = e;
        }
        grid_barrier(target);

        for (int j = tid; j < 1024; j += TPB) {
            const float* cp = g_colPart[pb] + (size_t)(tb * 8) * NN + j;
            float s0 = cp[0 * NN] + cp[1 * NN];
            float s1 = cp[2 * NN] + cp[3 * NN];
            float s2 = cp[4 * NN] + cp[5 * NN];
            float s3 = cp[6 * NN] + cp[7 * NN];
            float colSum = (s0 + s1) + (s2 + s3);
            float vo  = shV[j];
            float bo  = shB[j];
            float lse = __logf(fmaf(bo, colSum, 1e-6f));
            float vn  = EPSF * (log_mu - lse) + vo;
            shV[j] = vn;
            shB[j] = __expf(vn * inv_eps);
        }

        float ev = (tid < GRD) ? g_errPart[pb][tid] : 0.0f;
        ev = warp_sum(ev);
        if (lane == 0) shRed[w] = ev;
        __syncthreads();
        float err = (shRed[0] + shRed[1] + shRed[2] + shRed[3]) * (1.0f / BB);
        stop = (err < THRF);
        __syncthreads();
    }

    // ===== final: cost = sum_ij a_i * K_ij * b_j * C_ij =====
    {
        float acc = 0.0f;
        const int rowLocalBase = w * 8;
        #pragma unroll 2
        for (int r = 0; r < 8; r++) {
            const int rl  = rowLocalBase + r;
            const int row = bid * 128 + rl;
            const uint4* __restrict__ Kr = (const uint4*)(g_Kh + (size_t)row * NN);
            const uint4* __restrict__ Cr = (const uint4*)(g_Ch + (size_t)row * NN);
            ull s2 = 0ULL;
            #pragma unroll
            for (int tt = 0; tt < 4; tt++) {
                uint4 kq = Kr[lane + 32 * tt];
                uint4 cq = Cr[lane + 32 * tt];
                const __half2* kp = (const __half2*)&kq;
                const __half2* cp = (const __half2*)&cq;
                const ull* bp = (const ull*)(shB + ((lane + 32 * tt) << 3));
                #pragma unroll
                for (int e = 0; e < 4; e++) {
                    float2 kf = __half22float2(kp[e]);
                    float2 cf = __half22float2(cp[e]);
                    ull kb;
                    MUL2(kb, pk2(kf.x, kf.y), bp[e]);
                    FMA2(s2, kb, pk2(cf.x, cf.y));
                }
            }
            float sx, sy; up2(s2, sx, sy);
            float s = warp_sum(sx + sy);
            if (lane == 0) acc += __expf(shU[rl] * inv_eps) * s;
        }
        if (lane == 0) shRed[w] = acc;
        __syncthreads();
        if (tid == 0) {
            float e = 0.f;
            #pragma unroll
            for (int i = 0; i < 16; i++) e += shRed[i];
            atomicAdd(&g_cost, (double)e);
        }
        grid_barrier(target);
        if (bid == 0 && tid == 0) out[0] = (float)(g_cost * (1.0 / BB));
    }
}

// ---------------- launch ----------------
extern "C" void kernel_launch(void* const* d_in, const int* in_sizes, int n_in,
                              void* d_out, int out_size) {
    const float* x = (const float*)d_in[0];
    const float* y = (const float*)d_in[1];
    float* out = (float*)d_out;

    static int attrDone = 0;
    if (!attrDone) {
        cudaFuncSetAttribute(gemm_kernel,
                             cudaFuncAttributeMaxDynamicSharedMemorySize,
                             4 * TILEH * sizeof(__half));
        cudaFuncSetAttribute(sinkhorn_kernel,
                             cudaFuncAttributeMaxDynamicSharedMemorySize,
                             SH_FLOATS * sizeof(float));
        attrDone = 1;
    }

    softmax_kernel<<<(2 * BB * NN * 8) / 256, 256>>>(x, y);
    gemm_kernel<<<dim3(8, 8, BB), 256, 4 * TILEH * sizeof(__half)>>>();
    sinkhorn_kernel<<<GRD, TPB, SH_FLOATS * sizeof(float)>>>(out);
}